// round 13
// baseline (speedup 1.0000x reference)
#include <cuda_runtime.h>
#include <cuda_bf16.h>
#include <math.h>
#include <stdint.h>

#define VOCAB 50000
#define D 256
#define E_EDGES 4096
#define S_SEQ 9
#define NUM_ORDERS 3

// ---------------- scratch (device globals: allocation-free) ----------------
__device__ __align__(256) float g_var0[E_EDGES * D];
__device__ __align__(256) float g_var1[E_EDGES * D];
__device__ __align__(256) float g_tmpC[E_EDGES * D];
__device__ __align__(256) float g_tmpD[E_EDGES * D];
__device__ __align__(256) float g_rowloss[E_EDGES];
// bf16 hi/lo splits for the vocab GEMM
__device__ __align__(256) __nv_bfloat16 g_Ahi[E_EDGES * D];
__device__ __align__(256) __nv_bfloat16 g_Alo[E_EDGES * D];
__device__ __align__(256) __nv_bfloat16 g_Bhi[VOCAB * D];
__device__ __align__(256) __nv_bfloat16 g_Blo[VOCAB * D];
// bf16 hi/lo activations + transposed weights for the MLP GEMMs
__device__ __align__(256) __nv_bfloat16 g_hh[E_EDGES * D];
__device__ __align__(256) __nv_bfloat16 g_hl[E_EDGES * D];
__device__ __align__(256) __nv_bfloat16 g_hidh[E_EDGES * D];
__device__ __align__(256) __nv_bfloat16 g_hidl[E_EDGES * D];
__device__ __align__(256) __nv_bfloat16 g_W1th[D * D];
__device__ __align__(256) __nv_bfloat16 g_W1tl[D * D];
__device__ __align__(256) __nv_bfloat16 g_W2th[D * D];
__device__ __align__(256) __nv_bfloat16 g_W2tl[D * D];

// ---------------- helpers ----------------
__device__ __forceinline__ uint32_t smem_u32(const void* p) {
    uint32_t a;
    asm("{ .reg .u64 t; cvta.to.shared.u64 t, %1; cvt.u32.u64 %0, t; }"
        : "=r"(a) : "l"(p));
    return a;
}
__device__ __forceinline__ void cpa16(uint32_t saddr, const void* gptr, uint32_t ssize) {
    unsigned long long g = __cvta_generic_to_global(const_cast<void*>(gptr));
    asm volatile("cp.async.cg.shared.global [%0], [%1], 16, %2;"
                 :: "r"(saddr), "l"(g), "r"(ssize));
}
__device__ __forceinline__ void mma16816(float* c, const uint32_t* a, const uint32_t* b) {
    asm volatile("mma.sync.aligned.m16n8k16.row.col.f32.bf16.bf16.f32 "
                 "{%0,%1,%2,%3}, {%4,%5,%6,%7}, {%8,%9}, {%0,%1,%2,%3};"
                 : "+f"(c[0]), "+f"(c[1]), "+f"(c[2]), "+f"(c[3])
                 : "r"(a[0]), "r"(a[1]), "r"(a[2]), "r"(a[3]), "r"(b[0]), "r"(b[1]));
}
__device__ __forceinline__ void ldsm_x4(uint32_t* r, uint32_t addr) {
    asm volatile("ldmatrix.sync.aligned.m8n8.x4.shared.b16 {%0,%1,%2,%3}, [%4];"
                 : "=r"(r[0]), "=r"(r[1]), "=r"(r[2]), "=r"(r[3]) : "r"(addr));
}
__device__ __forceinline__ uint32_t swz(uint32_t row, uint32_t chunk) {
    return row * 128u + ((chunk ^ (row & 7u)) << 4);
}

// ---------------- init vars to 1.0 ----------------
__global__ void k_init(float* __restrict__ v0, float* __restrict__ v1) {
    int i = blockIdx.x * 256 + threadIdx.x;
    v0[i] = 1.0f;
    v1[i] = 1.0f;
}

// ---------------- hi/lo bf16 split ----------------
__global__ void k_split(const float* __restrict__ x, __nv_bfloat16* __restrict__ hi,
                        __nv_bfloat16* __restrict__ lo, int n) {
    int i = blockIdx.x * 256 + threadIdx.x;
    if (i < n) {
        float v = x[i];
        __nv_bfloat16 h = __float2bfloat16(v);
        hi[i] = h;
        lo[i] = __float2bfloat16(v - __bfloat162float(h));
    }
}

// ---------------- transpose + hi/lo split for weights: Wt[n][k] = W[k][n] ----------------
__global__ void k_splitT(const float* __restrict__ W, __nv_bfloat16* __restrict__ hi,
                         __nv_bfloat16* __restrict__ lo) {
    int i = blockIdx.x * 256 + threadIdx.x;   // i over D*D
    int k = i / D, n = i % D;
    float v = W[i];
    __nv_bfloat16 h = __float2bfloat16(v);
    hi[n * D + k] = h;
    lo[n * D + k] = __float2bfloat16(v - __bfloat162float(h));
}

// ---------------- encoder: gather + masked pool + out-token + LN -> bf16 hi/lo ----------------
__global__ void k_encoder(const float* __restrict__ node_emb,
                          const int* __restrict__ input_ids,
                          const float* __restrict__ input_mask,
                          const int* __restrict__ var_in_mask,
                          const int* __restrict__ var_in_batch,
                          const int* __restrict__ out_pos,
                          const float* __restrict__ ln_g,
                          const float* __restrict__ ln_b,
                          const float* __restrict__ var1,
                          __nv_bfloat16* __restrict__ hh,
                          __nv_bfloat16* __restrict__ hl) {
    int e = blockIdx.x;
    int d = threadIdx.x;
    int op = out_pos[e];

    float acc = 0.0f, msum = 0.0f, outv = 0.0f;
#pragma unroll
    for (int s = 0; s < S_SEQ; s++) {
        int idx = s * E_EDGES + e;
        float m = input_mask[idx];
        float val;
        if (var_in_mask[idx] >= 0) {
            int j = var_in_batch[idx];
            j = max(0, min(E_EDGES - 1, j));
            val = var1[j * D + d];
        } else {
            val = node_emb[(long long)input_ids[idx] * D + d];
        }
        acc += val * m;
        msum += m;
        if (s == op) outv = val;
    }
    float x = acc / fmaxf(msum, 1.0f) + outv;

    float v1s = x, v2s = x * x;
#pragma unroll
    for (int o = 16; o > 0; o >>= 1) {
        v1s += __shfl_down_sync(0xFFFFFFFFu, v1s, o);
        v2s += __shfl_down_sync(0xFFFFFFFFu, v2s, o);
    }
    __shared__ float red1[8], red2[8];
    int wid = d >> 5, lane = d & 31;
    if (lane == 0) { red1[wid] = v1s; red2[wid] = v2s; }
    __syncthreads();
    float tot1 = 0.0f, tot2 = 0.0f;
#pragma unroll
    for (int i = 0; i < 8; i++) { tot1 += red1[i]; tot2 += red2[i]; }
    float mu = tot1 * (1.0f / D);
    float var = tot2 * (1.0f / D) - mu * mu;
    float y = (x - mu) * rsqrtf(var + 1e-5f) * ln_g[d] + ln_b[d];
    __nv_bfloat16 yh = __float2bfloat16(y);
    hh[e * D + d] = yh;
    hl[e * D + d] = __float2bfloat16(y - __bfloat162float(yh));
}

// ================= MLP GEMM via HMMA hi/lo split (unchanged from R12) =========
#define MBM 128
#define MBN 128
#define MBK 64
#define MTILE_B (MBM * MBK * 2)
#define MSTAGE_B (4 * MTILE_B)
#define SMEM_MLP (2 * MSTAGE_B)      // 128 KB

__global__ __launch_bounds__(256, 1)
void k_mlp_mma(const __nv_bfloat16* __restrict__ Ahi, const __nv_bfloat16* __restrict__ Alo,
               const __nv_bfloat16* __restrict__ Bhi, const __nv_bfloat16* __restrict__ Blo,
               const float* __restrict__ bias, int mode,
               __nv_bfloat16* __restrict__ out_hi, __nv_bfloat16* __restrict__ out_lo,
               float* __restrict__ var0, float* __restrict__ var1,
               const int* __restrict__ orders, const int* __restrict__ types, int order) {
    extern __shared__ char smem[];
    const int tid = threadIdx.x;
    const int wid = tid >> 5, lane = tid & 31;
    const int bm = blockIdx.y * MBM;
    const int bn = blockIdx.x * MBN;
    const int wm = (wid & 1) * 64;
    const int wn = (wid >> 1) * 32;
    const uint32_t sbase = smem_u32(smem);

    float acc[4][4][4];
#pragma unroll
    for (int mt = 0; mt < 4; mt++)
#pragma unroll
        for (int nt = 0; nt < 4; nt++)
#pragma unroll
            for (int q = 0; q < 4; q++) acc[mt][nt][q] = 0.0f;

    auto load_stage = [&](int ci, int stg) {
        const int k0 = ci * MBK;
        const uint32_t sst = sbase + (uint32_t)stg * MSTAGE_B;
#pragma unroll
        for (int j = 0; j < 4; j++) {
            int i = tid + j * 256;
            int row = i >> 3, ch = i & 7;
            uint32_t so = swz(row, ch);
            size_t aoff = (size_t)(bm + row) * D + k0 + ch * 8;
            cpa16(sst + 0 * MTILE_B + so, Ahi + aoff, 16);
            cpa16(sst + 1 * MTILE_B + so, Alo + aoff, 16);
            size_t boff = (size_t)(bn + row) * D + k0 + ch * 8;
            cpa16(sst + 2 * MTILE_B + so, Bhi + boff, 16);
            cpa16(sst + 3 * MTILE_B + so, Blo + boff, 16);
        }
        asm volatile("cp.async.commit_group;" ::: "memory");
    };

    load_stage(0, 0);

    const int jj = lane >> 3;
    const int rr = lane & 7;

    const int NCH = D / MBK;   // 4
    for (int ci = 0; ci < NCH; ci++) {
        if (ci + 1 < NCH) {
            load_stage(ci + 1, (ci + 1) & 1);
            asm volatile("cp.async.wait_group 1;" ::: "memory");
        } else {
            asm volatile("cp.async.wait_group 0;" ::: "memory");
        }
        __syncthreads();

        const uint32_t sst = sbase + (uint32_t)(ci & 1) * MSTAGE_B;
#pragma unroll
        for (int kt = 0; kt < 4; kt++) {
            uint32_t a_hi[4][4], a_lo[4][4], b_hi[4][2], b_lo[4][2];
            {
                uint32_t arow = (uint32_t)(wm + (jj & 1) * 8 + rr);
                uint32_t ach = (uint32_t)(kt * 2 + (jj >> 1));
#pragma unroll
                for (int mt = 0; mt < 4; mt++) {
                    uint32_t so = swz(arow + mt * 16, ach);
                    ldsm_x4(a_hi[mt], sst + 0 * MTILE_B + so);
                    ldsm_x4(a_lo[mt], sst + 1 * MTILE_B + so);
                }
            }
            {
                uint32_t bch = (uint32_t)(kt * 2 + ((lane >> 3) & 1));
#pragma unroll
                for (int p = 0; p < 2; p++) {
                    uint32_t brow = (uint32_t)(wn + (2 * p + (lane >> 4)) * 8 + rr);
                    uint32_t so = swz(brow, bch);
                    uint32_t r4[4];
                    ldsm_x4(r4, sst + 2 * MTILE_B + so);
                    b_hi[2 * p][0] = r4[0]; b_hi[2 * p][1] = r4[1];
                    b_hi[2 * p + 1][0] = r4[2]; b_hi[2 * p + 1][1] = r4[3];
                    ldsm_x4(r4, sst + 3 * MTILE_B + so);
                    b_lo[2 * p][0] = r4[0]; b_lo[2 * p][1] = r4[1];
                    b_lo[2 * p + 1][0] = r4[2]; b_lo[2 * p + 1][1] = r4[3];
                }
            }
#pragma unroll
            for (int mt = 0; mt < 4; mt++)
#pragma unroll
                for (int nt = 0; nt < 4; nt++) {
                    mma16816(acc[mt][nt], a_hi[mt], b_hi[nt]);
                    mma16816(acc[mt][nt], a_hi[mt], b_lo[nt]);
                    mma16816(acc[mt][nt], a_lo[mt], b_hi[nt]);
                }
        }
        __syncthreads();
    }

    // ---- epilogue ----
    const int g = lane >> 2;
    const int qc = (lane & 3) * 2;
#pragma unroll
    for (int mt = 0; mt < 4; mt++) {
        int row0 = bm + wm + mt * 16 + g;
#pragma unroll
        for (int nt = 0; nt < 4; nt++) {
            int col = bn + wn + nt * 8 + qc;
            float b0 = bias[col], b1v = bias[col + 1];
            float v00 = acc[mt][nt][0] + b0;
            float v01 = acc[mt][nt][1] + b1v;
            float v10 = acc[mt][nt][2] + b0;
            float v11 = acc[mt][nt][3] + b1v;
            if (mode == 0) {
                v00 = fmaxf(v00, 0.0f); v01 = fmaxf(v01, 0.0f);
                v10 = fmaxf(v10, 0.0f); v11 = fmaxf(v11, 0.0f);
#pragma unroll
                for (int hrow = 0; hrow < 2; hrow++) {
                    int r = row0 + hrow * 8;
                    float a = hrow ? v10 : v00;
                    float b = hrow ? v11 : v01;
                    __nv_bfloat16 ah = __float2bfloat16(a);
                    __nv_bfloat16 bh = __float2bfloat16(b);
                    out_hi[(size_t)r * D + col] = ah;
                    out_hi[(size_t)r * D + col + 1] = bh;
                    out_lo[(size_t)r * D + col] = __float2bfloat16(a - __bfloat162float(ah));
                    out_lo[(size_t)r * D + col + 1] = __float2bfloat16(b - __bfloat162float(bh));
                }
            } else {
                v00 = 1.0f / (1.0f + __expf(-v00));
                v01 = 1.0f / (1.0f + __expf(-v01));
                v10 = 1.0f / (1.0f + __expf(-v10));
                v11 = 1.0f / (1.0f + __expf(-v11));
#pragma unroll
                for (int hrow = 0; hrow < 2; hrow++) {
                    int e = row0 + hrow * 8;
                    if (orders[e] == order) {
                        float a = hrow ? v10 : v00;
                        float b = hrow ? v11 : v01;
                        var0[(size_t)e * D + col] = a;
                        var0[(size_t)e * D + col + 1] = b;
                        bool neg = (types[e] == 1);
                        var1[(size_t)e * D + col] = neg ? (1.0f - a) : a;
                        var1[(size_t)e * D + col + 1] = neg ? (1.0f - b) : b;
                    }
                }
            }
        }
    }
}

// ---------------- conjunction ----------------
__global__ void k_conj(const float* __restrict__ var0, const float* __restrict__ var1,
                       const int* __restrict__ orders, const int* __restrict__ types,
                       const int* __restrict__ lin, const int* __restrict__ lib,
                       int order, float* __restrict__ tmpC) {
    int e = blockIdx.x;
    if (orders[e] != order || types[e] != 2) return;
    int d = threadIdx.x;
    float p = var0[e * D + d];
#pragma unroll
    for (int a = 1; a < 4; a++) {
        if (lin[a * E_EDGES + e] >= 0) {
            int j = lib[a * E_EDGES + e];
            j = max(0, min(E_EDGES - 1, j));
            p *= var1[j * D + d];
        }
    }
    tmpC[e * D + d] = p;
}

// ---------------- disjunction (sees post-conj var1 via tmpC redirect) ----------------
__global__ void k_disj(const float* __restrict__ var0, const float* __restrict__ var1,
                       const int* __restrict__ orders, const int* __restrict__ types,
                       const int* __restrict__ lin, const int* __restrict__ lib,
                       int order, const float* __restrict__ tmpC, float* __restrict__ tmpD) {
    int e = blockIdx.x;
    if (orders[e] != order || types[e] != 3) return;
    int d = threadIdx.x;
    float q = 1.0f - var0[e * D + d];
#pragma unroll
    for (int a = 1; a < 4; a++) {
        if (lin[a * E_EDGES + e] >= 0) {
            int j = lib[a * E_EDGES + e];
            j = max(0, min(E_EDGES - 1, j));
            float v = (orders[j] == order && types[j] == 2) ? tmpC[j * D + d]
                                                           : var1[j * D + d];
            q *= (1.0f - v);
        }
    }
    tmpD[e * D + d] = 1.0f - q;
}

// ---------------- apply conj/disj ----------------
__global__ void k_apply(const int* __restrict__ orders, const int* __restrict__ types,
                        int order, const float* __restrict__ tmpC,
                        const float* __restrict__ tmpD, float* __restrict__ var1) {
    int e = blockIdx.x;
    if (orders[e] != order) return;
    int ty = types[e];
    int d = threadIdx.x;
    if (ty == 2) var1[e * D + d] = tmpC[e * D + d];
    else if (ty == 3) var1[e * D + d] = tmpD[e * D + d];
}

// ================= warp-MMA vocab GEMM: 512 threads, 16 warps, 32x32 warp tile =
#define BMT 128
#define BNT 128
#define BKT 64
#define TILE_B (BMT * BKT * 2)
#define STAGE_B (4 * TILE_B)
#define SMEM_GEMM (2 * STAGE_B)      // 128 KB

__global__ __launch_bounds__(512, 1)
void k_gemm_mma(const __nv_bfloat16* __restrict__ Ahi, const __nv_bfloat16* __restrict__ Alo,
                const __nv_bfloat16* __restrict__ Bhi, const __nv_bfloat16* __restrict__ Blo,
                float* __restrict__ C) {
    extern __shared__ char smem[];
    const int tid = threadIdx.x;
    const int wid = tid >> 5, lane = tid & 31;
    const int bm = blockIdx.y * BMT;
    const int bn = blockIdx.x * BNT;
    const int wm = (wid & 3) * 32;     // 4 m-warps x 32 rows
    const int wn = (wid >> 2) * 32;    // 4 n-warps x 32 cols
    const uint32_t sbase = smem_u32(smem);

    float acc[2][4][4];
#pragma unroll
    for (int mt = 0; mt < 2; mt++)
#pragma unroll
        for (int nt = 0; nt < 4; nt++)
#pragma unroll
            for (int q = 0; q < 4; q++) acc[mt][nt][q] = 0.0f;

    auto load_stage = [&](int ci, int stg) {
        const int k0 = ci * BKT;
        const uint32_t sst = sbase + (uint32_t)stg * STAGE_B;
#pragma unroll
        for (int j = 0; j < 2; j++) {
            int i = tid + j * 512;
            int row = i >> 3, ch = i & 7;
            uint32_t so = swz(row, ch);
            size_t aoff = (size_t)(bm + row) * D + k0 + ch * 8;
            cpa16(sst + 0 * TILE_B + so, Ahi + aoff, 16);
            cpa16(sst + 1 * TILE_B + so, Alo + aoff, 16);
            int brow = bn + row;
            uint32_t bs = (brow < VOCAB) ? 16u : 0u;
            size_t boff = (size_t)min(brow, VOCAB - 1) * D + k0 + ch * 8;
            cpa16(sst + 2 * TILE_B + so, Bhi + boff, bs);
            cpa16(sst + 3 * TILE_B + so, Blo + boff, bs);
        }
        asm volatile("cp.async.commit_group;" ::: "memory");
    };

    load_stage(0, 0);

    const int jj = lane >> 3;
    const int rr = lane & 7;

    const int NCH = D / BKT;
    for (int ci = 0; ci < NCH; ci++) {
        if (ci + 1 < NCH) {
            load_stage(ci + 1, (ci + 1) & 1);
            asm volatile("cp.async.wait_group 1;" ::: "memory");
        } else {
            asm volatile("cp.async.wait_group 0;" ::: "memory");
        }
        __syncthreads();

        const uint32_t sst = sbase + (uint32_t)(ci & 1) * STAGE_B;
#pragma unroll
        for (int kt = 0; kt < 4; kt++) {
            uint32_t a_hi[2][4], a_lo[2][4], b_hi[4][2], b_lo[4][2];
            {
                uint32_t arow = (uint32_t)(wm + (jj & 1) * 8 + rr);
                uint32_t ach = (uint32_t)(kt * 2 + (jj >> 1));
#pragma unroll
                for (int mt = 0; mt < 2; mt++) {
                    uint32_t so = swz(arow + mt * 16, ach);
                    ldsm_x4(a_hi[mt], sst + 0 * TILE_B + so);
                    ldsm_x4(a_lo[mt], sst + 1 * TILE_B + so);
                }
            }
            {
                uint32_t bch = (uint32_t)(kt * 2 + ((lane >> 3) & 1));
#pragma unroll
                for (int p = 0; p < 2; p++) {
                    uint32_t brow = (uint32_t)(wn + (2 * p + (lane >> 4)) * 8 + rr);
                    uint32_t so = swz(brow, bch);
                    uint32_t r4[4];
                    ldsm_x4(r4, sst + 2 * TILE_B + so);
                    b_hi[2 * p][0] = r4[0]; b_hi[2 * p][1] = r4[1];
                    b_hi[2 * p + 1][0] = r4[2]; b_hi[2 * p + 1][1] = r4[3];
                    ldsm_x4(r4, sst + 3 * TILE_B + so);
                    b_lo[2 * p][0] = r4[0]; b_lo[2 * p][1] = r4[1];
                    b_lo[2 * p + 1][0] = r4[2]; b_lo[2 * p + 1][1] = r4[3];
                }
            }
#pragma unroll
            for (int mt = 0; mt < 2; mt++)
#pragma unroll
                for (int nt = 0; nt < 4; nt++) {
                    mma16816(acc[mt][nt], a_hi[mt], b_hi[nt]);
                    mma16816(acc[mt][nt], a_hi[mt], b_lo[nt]);
                    mma16816(acc[mt][nt], a_lo[mt], b_hi[nt]);
                }
        }
        __syncthreads();
    }

    // ---- epilogue: SCALAR stores (C base is 4B-aligned only: out+1) ----
    const int g = lane >> 2;
    const int qc = (lane & 3) * 2;
#pragma unroll
    for (int mt = 0; mt < 2; mt++) {
        int row0 = bm + wm + mt * 16 + g;
#pragma unroll
        for (int nt = 0; nt < 4; nt++) {
            int col = bn + wn + nt * 8 + qc;
            if (col < VOCAB) {
                float* p0 = &C[(size_t)row0 * VOCAB + col];
                float* p1 = &C[(size_t)(row0 + 8) * VOCAB + col];
                p0[0] = acc[mt][nt][0];
                p0[1] = acc[mt][nt][1];
                p1[0] = acc[mt][nt][2];
                p1[1] = acc[mt][nt][3];
            }
        }
    }
}

// ---------------- per-row soft-label CE via online logsumexp ----------------
__global__ void k_rowloss(const float* __restrict__ logits,
                          const int* __restrict__ answers,
                          const int* __restrict__ mask_type,
                          float* __restrict__ rowloss) {
    int e = blockIdx.x;
    const float* row = logits + (size_t)e * VOCAB;
    int t = threadIdx.x;
    float m = -1e30f, s = 0.0f, sx = 0.0f;
    for (int v = t; v < VOCAB; v += 256) {
        float x = row[v];
        sx += x;
        float mn = fmaxf(m, x);
        s = s * __expf(m - mn) + __expf(x - mn);
        m = mn;
    }
    __shared__ float shm[256], shs[256], shx[256];
    shm[t] = m; shs[t] = s; shx[t] = sx;
    __syncthreads();
    for (int off = 128; off > 0; off >>= 1) {
        if (t < off) {
            float m2 = shm[t + off], s2 = shs[t + off];
            float mn = fmaxf(shm[t], m2);
            shs[t] = shs[t] * __expf(shm[t] - mn) + s2 * __expf(m2 - mn);
            shm[t] = mn;
            shx[t] += shx[t + off];
        }
        __syncthreads();
    }
    if (t == 0) {
        float lse = shm[0] + logf(shs[0]);
        float sumx = shx[0];
        float la = row[answers[e]] - lse;
        float soft = (mask_type[e] > 0) ? 0.9f : 1.0f;
        float loss = -(soft * la +
                       (1.0f - soft) * (1.0f / (float)(VOCAB - 1)) *
                           ((sumx - (float)VOCAB * lse) - la));
        rowloss[e] = loss;
    }
}

__global__ void k_finalloss(const float* __restrict__ rowloss, float* __restrict__ out) {
    __shared__ float sh[256];
    float a = 0.0f;
    for (int i = threadIdx.x; i < E_EDGES; i += 256) a += rowloss[i];
    sh[threadIdx.x] = a;
    __syncthreads();
    for (int off = 128; off > 0; off >>= 1) {
        if (threadIdx.x < off) sh[threadIdx.x] += sh[threadIdx.x + off];
        __syncthreads();
    }
    if (threadIdx.x == 0) out[0] = sh[0] * (1.0f / (float)E_EDGES);
}

// ---------------- launch ----------------
extern "C" void kernel_launch(void* const* d_in, const int* in_sizes, int n_in,
                              void* d_out, int out_size) {
    const float* node_emb   = (const float*)d_in[0];
    const int*   input_ids  = (const int*)d_in[1];
    const float* input_mask = (const float*)d_in[2];
    const int*   edge_ord   = (const int*)d_in[3];
    const int*   vim        = (const int*)d_in[4];
    const int*   vibm       = (const int*)d_in[5];
    const int*   out_pos    = (const int*)d_in[6];
    const int*   lin        = (const int*)d_in[7];
    const int*   lib        = (const int*)d_in[8];
    const int*   ltypes     = (const int*)d_in[9];
    const int*   answers    = (const int*)d_in[10];
    const int*   mask_type  = (const int*)d_in[11];
    const float* W1         = (const float*)d_in[12];
    const float* b1         = (const float*)d_in[13];
    const float* W2         = (const float*)d_in[14];
    const float* b2         = (const float*)d_in[15];
    const float* ln_g       = (const float*)d_in[16];
    const float* ln_b       = (const float*)d_in[17];

    float* out = (float*)d_out;
    long long loff = (long long)out_size - (long long)E_EDGES * VOCAB;
    if (loff < 0) loff = 0;
    float* logits = out + loff;

    float *var0, *var1, *tmpC, *tmpD, *rowloss;
    __nv_bfloat16 *Ahi, *Alo, *Bhi, *Blo, *hh, *hl, *hidh, *hidl;
    __nv_bfloat16 *W1th, *W1tl, *W2th, *W2tl;
    cudaGetSymbolAddress((void**)&var0, g_var0);
    cudaGetSymbolAddress((void**)&var1, g_var1);
    cudaGetSymbolAddress((void**)&tmpC, g_tmpC);
    cudaGetSymbolAddress((void**)&tmpD, g_tmpD);
    cudaGetSymbolAddress((void**)&rowloss, g_rowloss);
    cudaGetSymbolAddress((void**)&Ahi, g_Ahi);
    cudaGetSymbolAddress((void**)&Alo, g_Alo);
    cudaGetSymbolAddress((void**)&Bhi, g_Bhi);
    cudaGetSymbolAddress((void**)&Blo, g_Blo);
    cudaGetSymbolAddress((void**)&hh, g_hh);
    cudaGetSymbolAddress((void**)&hl, g_hl);
    cudaGetSymbolAddress((void**)&hidh, g_hidh);
    cudaGetSymbolAddress((void**)&hidl, g_hidl);
    cudaGetSymbolAddress((void**)&W1th, g_W1th);
    cudaGetSymbolAddress((void**)&W1tl, g_W1tl);
    cudaGetSymbolAddress((void**)&W2th, g_W2th);
    cudaGetSymbolAddress((void**)&W2tl, g_W2tl);

    cudaFuncSetAttribute(k_gemm_mma, cudaFuncAttributeMaxDynamicSharedMemorySize,
                         SMEM_GEMM);
    cudaFuncSetAttribute(k_mlp_mma, cudaFuncAttributeMaxDynamicSharedMemorySize,
                         SMEM_MLP);

    k_init<<<(E_EDGES * D) / 256, 256>>>(var0, var1);
    k_split<<<(VOCAB * D + 255) / 256, 256>>>(node_emb, Bhi, Blo, VOCAB * D);
    k_splitT<<<(D * D) / 256, 256>>>(W1, W1th, W1tl);
    k_splitT<<<(D * D) / 256, 256>>>(W2, W2th, W2tl);

    dim3 mgrid(2, E_EDGES / MBM);
    for (int order = 0; order < NUM_ORDERS; ++order) {
        k_encoder<<<E_EDGES, 256>>>(node_emb, input_ids, input_mask, vim, vibm,
                                    out_pos, ln_g, ln_b, var1, hh, hl);
        k_mlp_mma<<<mgrid, 256, SMEM_MLP>>>(hh, hl, W1th, W1tl, b1, 0,
                                            hidh, hidl, nullptr, nullptr,
                                            nullptr, nullptr, 0);
        k_mlp_mma<<<mgrid, 256, SMEM_MLP>>>(hidh, hidl, W2th, W2tl, b2, 1,
                                            nullptr, nullptr, var0, var1,
                                            edge_ord, ltypes, order);
        k_conj<<<E_EDGES, 256>>>(var0, var1, edge_ord, ltypes, lin, lib, order, tmpC);
        k_disj<<<E_EDGES, 256>>>(var0, var1, edge_ord, ltypes, lin, lib, order, tmpC, tmpD);
        k_apply<<<E_EDGES, 256>>>(edge_ord, ltypes, order, tmpC, tmpD, var1);
    }

    k_split<<<(E_EDGES * D + 255) / 256, 256>>>(var1, Ahi, Alo, E_EDGES * D);

    dim3 grid((VOCAB + BNT - 1) / BNT, E_EDGES / BMT);
    k_gemm_mma<<<grid, 512, SMEM_GEMM>>>(Ahi, Alo, Bhi, Blo, logits);

    if (loff >= 1) {
        k_rowloss<<<E_EDGES, 256>>>(logits, answers, mask_type, rowloss);
        k_finalloss<<<1, 256>>>(rowloss, out);
    }
}

// round 16
// speedup vs baseline: 1.0934x; 1.0934x over previous
#include <cuda_runtime.h>
#include <cuda_bf16.h>
#include <math.h>
#include <stdint.h>

#define VOCAB 50000
#define D 256
#define E_EDGES 4096
#define S_SEQ 9
#define NUM_ORDERS 3

// ---------------- scratch (device globals: allocation-free) ----------------
__device__ __align__(256) float g_var0[E_EDGES * D];
__device__ __align__(256) float g_var1[E_EDGES * D];
__device__ __align__(256) float g_tmpC[E_EDGES * D];
__device__ __align__(256) float g_tmpD[E_EDGES * D];
__device__ __align__(256) float g_rowloss[E_EDGES];
// bf16 hi/lo splits for the vocab GEMM
__device__ __align__(256) __nv_bfloat16 g_Ahi[E_EDGES * D];
__device__ __align__(256) __nv_bfloat16 g_Alo[E_EDGES * D];
__device__ __align__(256) __nv_bfloat16 g_Bhi[VOCAB * D];
__device__ __align__(256) __nv_bfloat16 g_Blo[VOCAB * D];
// bf16 hi/lo activations + transposed weights for the MLP GEMMs
__device__ __align__(256) __nv_bfloat16 g_hh[E_EDGES * D];
__device__ __align__(256) __nv_bfloat16 g_hl[E_EDGES * D];
__device__ __align__(256) __nv_bfloat16 g_hidh[E_EDGES * D];
__device__ __align__(256) __nv_bfloat16 g_hidl[E_EDGES * D];
__device__ __align__(256) __nv_bfloat16 g_W1th[D * D];
__device__ __align__(256) __nv_bfloat16 g_W1tl[D * D];
__device__ __align__(256) __nv_bfloat16 g_W2th[D * D];
__device__ __align__(256) __nv_bfloat16 g_W2tl[D * D];

// ---------------- helpers ----------------
__device__ __forceinline__ uint32_t smem_u32(const void* p) {
    uint32_t a;
    asm("{ .reg .u64 t; cvta.to.shared.u64 t, %1; cvt.u32.u64 %0, t; }"
        : "=r"(a) : "l"(p));
    return a;
}
__device__ __forceinline__ void cpa16(uint32_t saddr, const void* gptr, uint32_t ssize) {
    unsigned long long g = __cvta_generic_to_global(const_cast<void*>(gptr));
    asm volatile("cp.async.cg.shared.global [%0], [%1], 16, %2;"
                 :: "r"(saddr), "l"(g), "r"(ssize));
}
__device__ __forceinline__ void mma16816(float* c, const uint32_t* a, const uint32_t* b) {
    asm volatile("mma.sync.aligned.m16n8k16.row.col.f32.bf16.bf16.f32 "
                 "{%0,%1,%2,%3}, {%4,%5,%6,%7}, {%8,%9}, {%0,%1,%2,%3};"
                 : "+f"(c[0]), "+f"(c[1]), "+f"(c[2]), "+f"(c[3])
                 : "r"(a[0]), "r"(a[1]), "r"(a[2]), "r"(a[3]), "r"(b[0]), "r"(b[1]));
}
__device__ __forceinline__ void ldsm_x4(uint32_t* r, uint32_t addr) {
    asm volatile("ldmatrix.sync.aligned.m8n8.x4.shared.b16 {%0,%1,%2,%3}, [%4];"
                 : "=r"(r[0]), "=r"(r[1]), "=r"(r[2]), "=r"(r[3]) : "r"(addr));
}
__device__ __forceinline__ uint32_t swz(uint32_t row, uint32_t chunk) {
    return row * 128u + ((chunk ^ (row & 7u)) << 4);
}

// ---------------- init vars to 1.0 ----------------
__global__ void k_init(float* __restrict__ v0, float* __restrict__ v1) {
    int i = blockIdx.x * 256 + threadIdx.x;
    v0[i] = 1.0f;
    v1[i] = 1.0f;
}

// ---------------- hi/lo bf16 split ----------------
__global__ void k_split(const float* __restrict__ x, __nv_bfloat16* __restrict__ hi,
                        __nv_bfloat16* __restrict__ lo, int n) {
    int i = blockIdx.x * 256 + threadIdx.x;
    if (i < n) {
        float v = x[i];
        __nv_bfloat16 h = __float2bfloat16(v);
        hi[i] = h;
        lo[i] = __float2bfloat16(v - __bfloat162float(h));
    }
}

// ---------------- transpose + hi/lo split for weights: Wt[n][k] = W[k][n] ----------------
__global__ void k_splitT(const float* __restrict__ W, __nv_bfloat16* __restrict__ hi,
                         __nv_bfloat16* __restrict__ lo) {
    int i = blockIdx.x * 256 + threadIdx.x;   // i over D*D
    int k = i / D, n = i % D;
    float v = W[i];
    __nv_bfloat16 h = __float2bfloat16(v);
    hi[n * D + k] = h;
    lo[n * D + k] = __float2bfloat16(v - __bfloat162float(h));
}

// ---------------- encoder: gather + masked pool + out-token + LN -> bf16 hi/lo ----------------
__global__ void k_encoder(const float* __restrict__ node_emb,
                          const int* __restrict__ input_ids,
                          const float* __restrict__ input_mask,
                          const int* __restrict__ var_in_mask,
                          const int* __restrict__ var_in_batch,
                          const int* __restrict__ out_pos,
                          const float* __restrict__ ln_g,
                          const float* __restrict__ ln_b,
                          const float* __restrict__ var1,
                          __nv_bfloat16* __restrict__ hh,
                          __nv_bfloat16* __restrict__ hl) {
    int e = blockIdx.x;
    int d = threadIdx.x;
    int op = out_pos[e];

    float acc = 0.0f, msum = 0.0f, outv = 0.0f;
#pragma unroll
    for (int s = 0; s < S_SEQ; s++) {
        int idx = s * E_EDGES + e;
        float m = input_mask[idx];
        float val;
        if (var_in_mask[idx] >= 0) {
            int j = var_in_batch[idx];
            j = max(0, min(E_EDGES - 1, j));
            val = var1[j * D + d];
        } else {
            val = node_emb[(long long)input_ids[idx] * D + d];
        }
        acc += val * m;
        msum += m;
        if (s == op) outv = val;
    }
    float x = acc / fmaxf(msum, 1.0f) + outv;

    float v1s = x, v2s = x * x;
#pragma unroll
    for (int o = 16; o > 0; o >>= 1) {
        v1s += __shfl_down_sync(0xFFFFFFFFu, v1s, o);
        v2s += __shfl_down_sync(0xFFFFFFFFu, v2s, o);
    }
    __shared__ float red1[8], red2[8];
    int wid = d >> 5, lane = d & 31;
    if (lane == 0) { red1[wid] = v1s; red2[wid] = v2s; }
    __syncthreads();
    float tot1 = 0.0f, tot2 = 0.0f;
#pragma unroll
    for (int i = 0; i < 8; i++) { tot1 += red1[i]; tot2 += red2[i]; }
    float mu = tot1 * (1.0f / D);
    float var = tot2 * (1.0f / D) - mu * mu;
    float y = (x - mu) * rsqrtf(var + 1e-5f) * ln_g[d] + ln_b[d];
    __nv_bfloat16 yh = __float2bfloat16(y);
    hh[e * D + d] = yh;
    hl[e * D + d] = __float2bfloat16(y - __bfloat162float(yh));
}

// ================= MLP GEMM via HMMA hi/lo split ======================
#define MBM 128
#define MBN 128
#define MBK 64
#define MTILE_B (MBM * MBK * 2)
#define MSTAGE_B (4 * MTILE_B)
#define SMEM_MLP (2 * MSTAGE_B)      // 128 KB

__global__ __launch_bounds__(256, 1)
void k_mlp_mma(const __nv_bfloat16* __restrict__ Ahi, const __nv_bfloat16* __restrict__ Alo,
               const __nv_bfloat16* __restrict__ Bhi, const __nv_bfloat16* __restrict__ Blo,
               const float* __restrict__ bias, int mode,
               __nv_bfloat16* __restrict__ out_hi, __nv_bfloat16* __restrict__ out_lo,
               float* __restrict__ var0, float* __restrict__ var1,
               const int* __restrict__ orders, const int* __restrict__ types, int order) {
    extern __shared__ char smem[];
    const int tid = threadIdx.x;
    const int wid = tid >> 5, lane = tid & 31;
    const int bm = blockIdx.y * MBM;
    const int bn = blockIdx.x * MBN;
    const int wm = (wid & 1) * 64;
    const int wn = (wid >> 1) * 32;
    const uint32_t sbase = smem_u32(smem);

    float acc[4][4][4];
#pragma unroll
    for (int mt = 0; mt < 4; mt++)
#pragma unroll
        for (int nt = 0; nt < 4; nt++)
#pragma unroll
            for (int q = 0; q < 4; q++) acc[mt][nt][q] = 0.0f;

    auto load_stage = [&](int ci, int stg) {
        const int k0 = ci * MBK;
        const uint32_t sst = sbase + (uint32_t)stg * MSTAGE_B;
#pragma unroll
        for (int j = 0; j < 4; j++) {
            int i = tid + j * 256;
            int row = i >> 3, ch = i & 7;
            uint32_t so = swz(row, ch);
            size_t aoff = (size_t)(bm + row) * D + k0 + ch * 8;
            cpa16(sst + 0 * MTILE_B + so, Ahi + aoff, 16);
            cpa16(sst + 1 * MTILE_B + so, Alo + aoff, 16);
            size_t boff = (size_t)(bn + row) * D + k0 + ch * 8;
            cpa16(sst + 2 * MTILE_B + so, Bhi + boff, 16);
            cpa16(sst + 3 * MTILE_B + so, Blo + boff, 16);
        }
        asm volatile("cp.async.commit_group;" ::: "memory");
    };

    load_stage(0, 0);

    const int jj = lane >> 3;
    const int rr = lane & 7;

    const int NCH = D / MBK;   // 4
    for (int ci = 0; ci < NCH; ci++) {
        if (ci + 1 < NCH) {
            load_stage(ci + 1, (ci + 1) & 1);
            asm volatile("cp.async.wait_group 1;" ::: "memory");
        } else {
            asm volatile("cp.async.wait_group 0;" ::: "memory");
        }
        __syncthreads();

        const uint32_t sst = sbase + (uint32_t)(ci & 1) * MSTAGE_B;
#pragma unroll
        for (int kt = 0; kt < 4; kt++) {
            uint32_t a_hi[4][4], a_lo[4][4], b_hi[4][2], b_lo[4][2];
            {
                uint32_t arow = (uint32_t)(wm + (jj & 1) * 8 + rr);
                uint32_t ach = (uint32_t)(kt * 2 + (jj >> 1));
#pragma unroll
                for (int mt = 0; mt < 4; mt++) {
                    uint32_t so = swz(arow + mt * 16, ach);
                    ldsm_x4(a_hi[mt], sst + 0 * MTILE_B + so);
                    ldsm_x4(a_lo[mt], sst + 1 * MTILE_B + so);
                }
            }
            {
                uint32_t bch = (uint32_t)(kt * 2 + ((lane >> 3) & 1));
#pragma unroll
                for (int p = 0; p < 2; p++) {
                    uint32_t brow = (uint32_t)(wn + (2 * p + (lane >> 4)) * 8 + rr);
                    uint32_t so = swz(brow, bch);
                    uint32_t r4[4];
                    ldsm_x4(r4, sst + 2 * MTILE_B + so);
                    b_hi[2 * p][0] = r4[0]; b_hi[2 * p][1] = r4[1];
                    b_hi[2 * p + 1][0] = r4[2]; b_hi[2 * p + 1][1] = r4[3];
                    ldsm_x4(r4, sst + 3 * MTILE_B + so);
                    b_lo[2 * p][0] = r4[0]; b_lo[2 * p][1] = r4[1];
                    b_lo[2 * p + 1][0] = r4[2]; b_lo[2 * p + 1][1] = r4[3];
                }
            }
            // pass-outer ordering: consecutive MMAs hit different accumulators
#pragma unroll
            for (int pass = 0; pass < 3; pass++)
#pragma unroll
                for (int mt = 0; mt < 4; mt++)
#pragma unroll
                    for (int nt = 0; nt < 4; nt++) {
                        const uint32_t* a = (pass == 2) ? a_lo[mt] : a_hi[mt];
                        const uint32_t* b = (pass == 1) ? b_lo[nt] : b_hi[nt];
                        mma16816(acc[mt][nt], a, b);
                    }
        }
        __syncthreads();
    }

    // ---- epilogue ----
    const int g = lane >> 2;
    const int qc = (lane & 3) * 2;
#pragma unroll
    for (int mt = 0; mt < 4; mt++) {
        int row0 = bm + wm + mt * 16 + g;
#pragma unroll
        for (int nt = 0; nt < 4; nt++) {
            int col = bn + wn + nt * 8 + qc;
            float b0 = bias[col], b1v = bias[col + 1];
            float v00 = acc[mt][nt][0] + b0;
            float v01 = acc[mt][nt][1] + b1v;
            float v10 = acc[mt][nt][2] + b0;
            float v11 = acc[mt][nt][3] + b1v;
            if (mode == 0) {
                v00 = fmaxf(v00, 0.0f); v01 = fmaxf(v01, 0.0f);
                v10 = fmaxf(v10, 0.0f); v11 = fmaxf(v11, 0.0f);
#pragma unroll
                for (int hrow = 0; hrow < 2; hrow++) {
                    int r = row0 + hrow * 8;
                    float a = hrow ? v10 : v00;
                    float b = hrow ? v11 : v01;
                    __nv_bfloat16 ah = __float2bfloat16(a);
                    __nv_bfloat16 bh = __float2bfloat16(b);
                    out_hi[(size_t)r * D + col] = ah;
                    out_hi[(size_t)r * D + col + 1] = bh;
                    out_lo[(size_t)r * D + col] = __float2bfloat16(a - __bfloat162float(ah));
                    out_lo[(size_t)r * D + col + 1] = __float2bfloat16(b - __bfloat162float(bh));
                }
            } else {
                v00 = 1.0f / (1.0f + __expf(-v00));
                v01 = 1.0f / (1.0f + __expf(-v01));
                v10 = 1.0f / (1.0f + __expf(-v10));
                v11 = 1.0f / (1.0f + __expf(-v11));
#pragma unroll
                for (int hrow = 0; hrow < 2; hrow++) {
                    int e = row0 + hrow * 8;
                    if (orders[e] == order) {
                        float a = hrow ? v10 : v00;
                        float b = hrow ? v11 : v01;
                        var0[(size_t)e * D + col] = a;
                        var0[(size_t)e * D + col + 1] = b;
                        bool neg = (types[e] == 1);
                        var1[(size_t)e * D + col] = neg ? (1.0f - a) : a;
                        var1[(size_t)e * D + col + 1] = neg ? (1.0f - b) : b;
                    }
                }
            }
        }
    }
}

// ---------------- conjunction ----------------
__global__ void k_conj(const float* __restrict__ var0, const float* __restrict__ var1,
                       const int* __restrict__ orders, const int* __restrict__ types,
                       const int* __restrict__ lin, const int* __restrict__ lib,
                       int order, float* __restrict__ tmpC) {
    int e = blockIdx.x;
    if (orders[e] != order || types[e] != 2) return;
    int d = threadIdx.x;
    float p = var0[e * D + d];
#pragma unroll
    for (int a = 1; a < 4; a++) {
        if (lin[a * E_EDGES + e] >= 0) {
            int j = lib[a * E_EDGES + e];
            j = max(0, min(E_EDGES - 1, j));
            p *= var1[j * D + d];
        }
    }
    tmpC[e * D + d] = p;
}

// ---------------- disjunction (sees post-conj var1 via tmpC redirect) ----------------
__global__ void k_disj(const float* __restrict__ var0, const float* __restrict__ var1,
                       const int* __restrict__ orders, const int* __restrict__ types,
                       const int* __restrict__ lin, const int* __restrict__ lib,
                       int order, const float* __restrict__ tmpC, float* __restrict__ tmpD) {
    int e = blockIdx.x;
    if (orders[e] != order || types[e] != 3) return;
    int d = threadIdx.x;
    float q = 1.0f - var0[e * D + d];
#pragma unroll
    for (int a = 1; a < 4; a++) {
        if (lin[a * E_EDGES + e] >= 0) {
            int j = lib[a * E_EDGES + e];
            j = max(0, min(E_EDGES - 1, j));
            float v = (orders[j] == order && types[j] == 2) ? tmpC[j * D + d]
                                                           : var1[j * D + d];
            q *= (1.0f - v);
        }
    }
    tmpD[e * D + d] = 1.0f - q;
}

// ---------------- apply conj/disj ----------------
__global__ void k_apply(const int* __restrict__ orders, const int* __restrict__ types,
                        int order, const float* __restrict__ tmpC,
                        const float* __restrict__ tmpD, float* __restrict__ var1) {
    int e = blockIdx.x;
    if (orders[e] != order) return;
    int ty = types[e];
    int d = threadIdx.x;
    if (ty == 2) var1[e * D + d] = tmpC[e * D + d];
    else if (ty == 3) var1[e * D + d] = tmpD[e * D + d];
}

// ================= warp-MMA (bf16 HMMA) vocab GEMM: R12 config + pass-outer MMAs
#define BMT 128
#define BNT 128
#define BKT 64
#define TILE_B (BMT * BKT * 2)
#define STAGE_B (4 * TILE_B)
#define SMEM_GEMM (2 * STAGE_B)      // 128 KB

__global__ __launch_bounds__(256, 1)
void k_gemm_mma(const __nv_bfloat16* __restrict__ Ahi, const __nv_bfloat16* __restrict__ Alo,
                const __nv_bfloat16* __restrict__ Bhi, const __nv_bfloat16* __restrict__ Blo,
                float* __restrict__ C) {
    extern __shared__ char smem[];
    const int tid = threadIdx.x;
    const int wid = tid >> 5, lane = tid & 31;
    const int bm = blockIdx.y * BMT;
    const int bn = blockIdx.x * BNT;
    const int wm = (wid & 1) * 64;
    const int wn = (wid >> 1) * 32;
    const uint32_t sbase = smem_u32(smem);

    float acc[4][4][4];
#pragma unroll
    for (int mt = 0; mt < 4; mt++)
#pragma unroll
        for (int nt = 0; nt < 4; nt++)
#pragma unroll
            for (int q = 0; q < 4; q++) acc[mt][nt][q] = 0.0f;

    auto load_stage = [&](int ci, int stg) {
        const int k0 = ci * BKT;
        const uint32_t sst = sbase + (uint32_t)stg * STAGE_B;
#pragma unroll
        for (int j = 0; j < 4; j++) {
            int i = tid + j * 256;
            int row = i >> 3, ch = i & 7;
            uint32_t so = swz(row, ch);
            size_t aoff = (size_t)(bm + row) * D + k0 + ch * 8;
            cpa16(sst + 0 * TILE_B + so, Ahi + aoff, 16);
            cpa16(sst + 1 * TILE_B + so, Alo + aoff, 16);
            int brow = bn + row;
            uint32_t bs = (brow < VOCAB) ? 16u : 0u;
            size_t boff = (size_t)min(brow, VOCAB - 1) * D + k0 + ch * 8;
            cpa16(sst + 2 * TILE_B + so, Bhi + boff, bs);
            cpa16(sst + 3 * TILE_B + so, Blo + boff, bs);
        }
        asm volatile("cp.async.commit_group;" ::: "memory");
    };

    load_stage(0, 0);

    const int jj = lane >> 3;
    const int rr = lane & 7;

    const int NCH = D / BKT;
    for (int ci = 0; ci < NCH; ci++) {
        if (ci + 1 < NCH) {
            load_stage(ci + 1, (ci + 1) & 1);
            asm volatile("cp.async.wait_group 1;" ::: "memory");
        } else {
            asm volatile("cp.async.wait_group 0;" ::: "memory");
        }
        __syncthreads();

        const uint32_t sst = sbase + (uint32_t)(ci & 1) * STAGE_B;
#pragma unroll
        for (int kt = 0; kt < 4; kt++) {
            uint32_t a_hi[4][4], a_lo[4][4], b_hi[4][2], b_lo[4][2];
            {
                uint32_t arow = (uint32_t)(wm + (jj & 1) * 8 + rr);
                uint32_t ach = (uint32_t)(kt * 2 + (jj >> 1));
#pragma unroll
                for (int mt = 0; mt < 4; mt++) {
                    uint32_t so = swz(arow + mt * 16, ach);
                    ldsm_x4(a_hi[mt], sst + 0 * TILE_B + so);
                    ldsm_x4(a_lo[mt], sst + 1 * TILE_B + so);
                }
            }
            {
                uint32_t bch = (uint32_t)(kt * 2 + ((lane >> 3) & 1));
#pragma unroll
                for (int p = 0; p < 2; p++) {
                    uint32_t brow = (uint32_t)(wn + (2 * p + (lane >> 4)) * 8 + rr);
                    uint32_t so = swz(brow, bch);
                    uint32_t r4[4];
                    ldsm_x4(r4, sst + 2 * TILE_B + so);
                    b_hi[2 * p][0] = r4[0]; b_hi[2 * p][1] = r4[1];
                    b_hi[2 * p + 1][0] = r4[2]; b_hi[2 * p + 1][1] = r4[3];
                    ldsm_x4(r4, sst + 3 * TILE_B + so);
                    b_lo[2 * p][0] = r4[0]; b_lo[2 * p][1] = r4[1];
                    b_lo[2 * p + 1][0] = r4[2]; b_lo[2 * p + 1][1] = r4[3];
                }
            }
            // pass-outer ordering: consecutive MMAs hit different accumulators;
            // same-acc reuse distance = 16 instructions (RAW latency hidden)
#pragma unroll
            for (int pass = 0; pass < 3; pass++)
#pragma unroll
                for (int mt = 0; mt < 4; mt++)
#pragma unroll
                    for (int nt = 0; nt < 4; nt++) {
                        const uint32_t* a = (pass == 2) ? a_lo[mt] : a_hi[mt];
                        const uint32_t* b = (pass == 1) ? b_lo[nt] : b_hi[nt];
                        mma16816(acc[mt][nt], a, b);
                    }
        }
        __syncthreads();
    }

    // ---- epilogue: SCALAR stores (C base is 4B-aligned only: out+1) ----
    const int g = lane >> 2;
    const int qc = (lane & 3) * 2;
#pragma unroll
    for (int mt = 0; mt < 4; mt++) {
        int row0 = bm + wm + mt * 16 + g;
#pragma unroll
        for (int nt = 0; nt < 4; nt++) {
            int col = bn + wn + nt * 8 + qc;
            if (col < VOCAB) {
                float* p0 = &C[(size_t)row0 * VOCAB + col];
                float* p1 = &C[(size_t)(row0 + 8) * VOCAB + col];
                p0[0] = acc[mt][nt][0];
                p0[1] = acc[mt][nt][1];
                p1[0] = acc[mt][nt][2];
                p1[1] = acc[mt][nt][3];
            }
        }
    }
}

// ---------------- per-row soft-label CE via online logsumexp ----------------
__global__ void k_rowloss(const float* __restrict__ logits,
                          const int* __restrict__ answers,
                          const int* __restrict__ mask_type,
                          float* __restrict__ rowloss) {
    int e = blockIdx.x;
    const float* row = logits + (size_t)e * VOCAB;
    int t = threadIdx.x;
    float m = -1e30f, s = 0.0f, sx = 0.0f;
    for (int v = t; v < VOCAB; v += 256) {
        float x = row[v];
        sx += x;
        float mn = fmaxf(m, x);
        s = s * __expf(m - mn) + __expf(x - mn);
        m = mn;
    }
    __shared__ float shm[256], shs[256], shx[256];
    shm[t] = m; shs[t] = s; shx[t] = sx;
    __syncthreads();
    for (int off = 128; off > 0; off >>= 1) {
        if (t < off) {
            float m2 = shm[t + off], s2 = shs[t + off];
            float mn = fmaxf(shm[t], m2);
            shs[t] = shs[t] * __expf(shm[t] - mn) + s2 * __expf(m2 - mn);
            shm[t] = mn;
            shx[t] += shx[t + off];
        }
        __syncthreads();
    }
    if (t == 0) {
        float lse = shm[0] + logf(shs[0]);
        float sumx = shx[0];
        float la = row[answers[e]] - lse;
        float soft = (mask_type[e] > 0) ? 0.9f : 1.0f;
        float loss = -(soft * la +
                       (1.0f - soft) * (1.0f / (float)(VOCAB - 1)) *
                           ((sumx - (float)VOCAB * lse) - la));
        rowloss[e] = loss;
    }
}

__global__ void k_finalloss(const float* __restrict__ rowloss, float* __restrict__ out) {
    __shared__ float sh[256];
    float a = 0.0f;
    for (int i = threadIdx.x; i < E_EDGES; i += 256) a += rowloss[i];
    sh[threadIdx.x] = a;
    __syncthreads();
    for (int off = 128; off > 0; off >>= 1) {
        if (threadIdx.x < off) sh[threadIdx.x] += sh[threadIdx.x + off];
        __syncthreads();
    }
    if (threadIdx.x == 0) out[0] = sh[0] * (1.0f / (float)E_EDGES);
}

// ---------------- launch ----------------
extern "C" void kernel_launch(void* const* d_in, const int* in_sizes, int n_in,
                              void* d_out, int out_size) {
    const float* node_emb   = (const float*)d_in[0];
    const int*   input_ids  = (const int*)d_in[1];
    const float* input_mask = (const float*)d_in[2];
    const int*   edge_ord   = (const int*)d_in[3];
    const int*   vim        = (const int*)d_in[4];
    const int*   vibm       = (const int*)d_in[5];
    const int*   out_pos    = (const int*)d_in[6];
    const int*   lin        = (const int*)d_in[7];
    const int*   lib        = (const int*)d_in[8];
    const int*   ltypes     = (const int*)d_in[9];
    const int*   answers    = (const int*)d_in[10];
    const int*   mask_type  = (const int*)d_in[11];
    const float* W1         = (const float*)d_in[12];
    const float* b1         = (const float*)d_in[13];
    const float* W2         = (const float*)d_in[14];
    const float* b2         = (const float*)d_in[15];
    const float* ln_g       = (const float*)d_in[16];
    const float* ln_b       = (const float*)d_in[17];

    float* out = (float*)d_out;
    long long loff = (long long)out_size - (long long)E_EDGES * VOCAB;
    if (loff < 0) loff = 0;
    float* logits = out + loff;

    float *var0, *var1, *tmpC, *tmpD, *rowloss;
    __nv_bfloat16 *Ahi, *Alo, *Bhi, *Blo, *hh, *hl, *hidh, *hidl;
    __nv_bfloat16 *W1th, *W1tl, *W2th, *W2tl;
    cudaGetSymbolAddress((void**)&var0, g_var0);
    cudaGetSymbolAddress((void**)&var1, g_var1);
    cudaGetSymbolAddress((void**)&tmpC, g_tmpC);
    cudaGetSymbolAddress((void**)&tmpD, g_tmpD);
    cudaGetSymbolAddress((void**)&rowloss, g_rowloss);
    cudaGetSymbolAddress((void**)&Ahi, g_Ahi);
    cudaGetSymbolAddress((void**)&Alo, g_Alo);
    cudaGetSymbolAddress((void**)&Bhi, g_Bhi);
    cudaGetSymbolAddress((void**)&Blo, g_Blo);
    cudaGetSymbolAddress((void**)&hh, g_hh);
    cudaGetSymbolAddress((void**)&hl, g_hl);
    cudaGetSymbolAddress((void**)&hidh, g_hidh);
    cudaGetSymbolAddress((void**)&hidl, g_hidl);
    cudaGetSymbolAddress((void**)&W1th, g_W1th);
    cudaGetSymbolAddress((void**)&W1tl, g_W1tl);
    cudaGetSymbolAddress((void**)&W2th, g_W2th);
    cudaGetSymbolAddress((void**)&W2tl, g_W2tl);

    cudaFuncSetAttribute(k_gemm_mma, cudaFuncAttributeMaxDynamicSharedMemorySize,
                         SMEM_GEMM);
    cudaFuncSetAttribute(k_mlp_mma, cudaFuncAttributeMaxDynamicSharedMemorySize,
                         SMEM_MLP);

    k_init<<<(E_EDGES * D) / 256, 256>>>(var0, var1);
    k_split<<<(VOCAB * D + 255) / 256, 256>>>(node_emb, Bhi, Blo, VOCAB * D);
    k_splitT<<<(D * D) / 256, 256>>>(W1, W1th, W1tl);
    k_splitT<<<(D * D) / 256, 256>>>(W2, W2th, W2tl);

    dim3 mgrid(2, E_EDGES / MBM);
    for (int order = 0; order < NUM_ORDERS; ++order) {
        k_encoder<<<E_EDGES, 256>>>(node_emb, input_ids, input_mask, vim, vibm,
                                    out_pos, ln_g, ln_b, var1, hh, hl);
        k_mlp_mma<<<mgrid, 256, SMEM_MLP>>>(hh, hl, W1th, W1tl, b1, 0,
                                            hidh, hidl, nullptr, nullptr,
                                            nullptr, nullptr, 0);
        k_mlp_mma<<<mgrid, 256, SMEM_MLP>>>(hidh, hidl, W2th, W2tl, b2, 1,
                                            nullptr, nullptr, var0, var1,
                                            edge_ord, ltypes, order);
        k_conj<<<E_EDGES, 256>>>(var0, var1, edge_ord, ltypes, lin, lib, order, tmpC);
        k_disj<<<E_EDGES, 256>>>(var0, var1, edge_ord, ltypes, lin, lib, order, tmpC, tmpD);
        k_apply<<<E_EDGES, 256>>>(edge_ord, ltypes, order, tmpC, tmpD, var1);
    }

    k_split<<<(E_EDGES * D + 255) / 256, 256>>>(var1, Ahi, Alo, E_EDGES * D);

    dim3 grid((VOCAB + BNT - 1) / BNT, E_EDGES / BMT);
    k_gemm_mma<<<grid, 256, SMEM_GEMM>>>(Ahi, Alo, Bhi, Blo, logits);

    if (loff >= 1) {
        k_rowloss<<<E_EDGES, 256>>>(logits, answers, mask_type, rowloss);
        k_finalloss<<<1, 256>>>(rowloss, out);
    }
}

// round 17
// speedup vs baseline: 1.2855x; 1.1757x over previous
#include <cuda_runtime.h>
#include <cuda_bf16.h>
#include <cuda_fp16.h>
#include <math.h>
#include <stdint.h>

#define VOCAB 50000
#define D 256
#define E_EDGES 4096
#define S_SEQ 9
#define NUM_ORDERS 3

// ---------------- scratch (device globals: allocation-free) ----------------
__device__ __align__(256) float g_var0[E_EDGES * D];
__device__ __align__(256) float g_var1[E_EDGES * D];
__device__ __align__(256) float g_tmpC[E_EDGES * D];
__device__ __align__(256) float g_tmpD[E_EDGES * D];
__device__ __align__(256) float g_rowloss[E_EDGES];
// fp16 operands for the vocab GEMM (A 2-way split, B single)
__device__ __align__(256) __half g_Ah[E_EDGES * D];
__device__ __align__(256) __half g_Al[E_EDGES * D];
__device__ __align__(256) __half g_Bh[VOCAB * D];
// bf16 hi/lo activations + transposed weights for the MLP GEMMs
__device__ __align__(256) __nv_bfloat16 g_hh[E_EDGES * D];
__device__ __align__(256) __nv_bfloat16 g_hl[E_EDGES * D];
__device__ __align__(256) __nv_bfloat16 g_hidh[E_EDGES * D];
__device__ __align__(256) __nv_bfloat16 g_hidl[E_EDGES * D];
__device__ __align__(256) __nv_bfloat16 g_W1th[D * D];
__device__ __align__(256) __nv_bfloat16 g_W1tl[D * D];
__device__ __align__(256) __nv_bfloat16 g_W2th[D * D];
__device__ __align__(256) __nv_bfloat16 g_W2tl[D * D];

// ---------------- helpers ----------------
__device__ __forceinline__ uint32_t smem_u32(const void* p) {
    uint32_t a;
    asm("{ .reg .u64 t; cvta.to.shared.u64 t, %1; cvt.u32.u64 %0, t; }"
        : "=r"(a) : "l"(p));
    return a;
}
__device__ __forceinline__ void cpa16(uint32_t saddr, const void* gptr, uint32_t ssize) {
    unsigned long long g = __cvta_generic_to_global(const_cast<void*>(gptr));
    asm volatile("cp.async.cg.shared.global [%0], [%1], 16, %2;"
                 :: "r"(saddr), "l"(g), "r"(ssize));
}
__device__ __forceinline__ void mma16816_bf16(float* c, const uint32_t* a, const uint32_t* b) {
    asm volatile("mma.sync.aligned.m16n8k16.row.col.f32.bf16.bf16.f32 "
                 "{%0,%1,%2,%3}, {%4,%5,%6,%7}, {%8,%9}, {%0,%1,%2,%3};"
                 : "+f"(c[0]), "+f"(c[1]), "+f"(c[2]), "+f"(c[3])
                 : "r"(a[0]), "r"(a[1]), "r"(a[2]), "r"(a[3]), "r"(b[0]), "r"(b[1]));
}
__device__ __forceinline__ void mma16816_f16(float* c, const uint32_t* a, const uint32_t* b) {
    asm volatile("mma.sync.aligned.m16n8k16.row.col.f32.f16.f16.f32 "
                 "{%0,%1,%2,%3}, {%4,%5,%6,%7}, {%8,%9}, {%0,%1,%2,%3};"
                 : "+f"(c[0]), "+f"(c[1]), "+f"(c[2]), "+f"(c[3])
                 : "r"(a[0]), "r"(a[1]), "r"(a[2]), "r"(a[3]), "r"(b[0]), "r"(b[1]));
}
__device__ __forceinline__ void ldsm_x4(uint32_t* r, uint32_t addr) {
    asm volatile("ldmatrix.sync.aligned.m8n8.x4.shared.b16 {%0,%1,%2,%3}, [%4];"
                 : "=r"(r[0]), "=r"(r[1]), "=r"(r[2]), "=r"(r[3]) : "r"(addr));
}
__device__ __forceinline__ uint32_t swz(uint32_t row, uint32_t chunk) {
    return row * 128u + ((chunk ^ (row & 7u)) << 4);
}

// ---------------- init vars to 1.0 ----------------
__global__ void k_init(float* __restrict__ v0, float* __restrict__ v1) {
    int i = blockIdx.x * 256 + threadIdx.x;
    v0[i] = 1.0f;
    v1[i] = 1.0f;
}

// ---------------- fp16 splits for the vocab GEMM ----------------
__global__ void k_splitA_h(const float* __restrict__ x, __half* __restrict__ hi,
                           __half* __restrict__ lo, int n) {
    int i = blockIdx.x * 256 + threadIdx.x;
    if (i < n) {
        float v = x[i];
        __half h = __float2half(v);
        hi[i] = h;
        lo[i] = __float2half(v - __half2float(h));
    }
}
__global__ void k_splitB_h(const float* __restrict__ x, __half* __restrict__ o, int n) {
    int i = blockIdx.x * 256 + threadIdx.x;
    if (i < n) o[i] = __float2half(x[i]);
}

// ---------------- transpose + bf16 hi/lo split for BOTH weight matrices ----------------
__global__ void k_splitT2(const float* __restrict__ W1, const float* __restrict__ W2,
                          __nv_bfloat16* __restrict__ h1, __nv_bfloat16* __restrict__ l1,
                          __nv_bfloat16* __restrict__ h2, __nv_bfloat16* __restrict__ l2) {
    int b = blockIdx.x;
    int i = (b & 255) * 256 + threadIdx.x;   // index in D*D
    const float* W = (b < 256) ? W1 : W2;
    __nv_bfloat16* hi = (b < 256) ? h1 : h2;
    __nv_bfloat16* lo = (b < 256) ? l1 : l2;
    int k = i / D, n = i % D;
    float v = W[i];
    __nv_bfloat16 h = __float2bfloat16(v);
    hi[n * D + k] = h;
    lo[n * D + k] = __float2bfloat16(v - __bfloat162float(h));
}

// ---------------- encoder: gather + masked pool + out-token + LN -> bf16 hi/lo ----------------
__global__ void k_encoder(const float* __restrict__ node_emb,
                          const int* __restrict__ input_ids,
                          const float* __restrict__ input_mask,
                          const int* __restrict__ var_in_mask,
                          const int* __restrict__ var_in_batch,
                          const int* __restrict__ out_pos,
                          const float* __restrict__ ln_g,
                          const float* __restrict__ ln_b,
                          const float* __restrict__ var1,
                          __nv_bfloat16* __restrict__ hh,
                          __nv_bfloat16* __restrict__ hl) {
    int e = blockIdx.x;
    int d = threadIdx.x;
    int op = out_pos[e];

    float acc = 0.0f, msum = 0.0f, outv = 0.0f;
#pragma unroll
    for (int s = 0; s < S_SEQ; s++) {
        int idx = s * E_EDGES + e;
        float m = input_mask[idx];
        float val;
        if (var_in_mask[idx] >= 0) {
            int j = var_in_batch[idx];
            j = max(0, min(E_EDGES - 1, j));
            val = var1[j * D + d];
        } else {
            val = node_emb[(long long)input_ids[idx] * D + d];
        }
        acc += val * m;
        msum += m;
        if (s == op) outv = val;
    }
    float x = acc / fmaxf(msum, 1.0f) + outv;

    float v1s = x, v2s = x * x;
#pragma unroll
    for (int o = 16; o > 0; o >>= 1) {
        v1s += __shfl_down_sync(0xFFFFFFFFu, v1s, o);
        v2s += __shfl_down_sync(0xFFFFFFFFu, v2s, o);
    }
    __shared__ float red1[8], red2[8];
    int wid = d >> 5, lane = d & 31;
    if (lane == 0) { red1[wid] = v1s; red2[wid] = v2s; }
    __syncthreads();
    float tot1 = 0.0f, tot2 = 0.0f;
#pragma unroll
    for (int i = 0; i < 8; i++) { tot1 += red1[i]; tot2 += red2[i]; }
    float mu = tot1 * (1.0f / D);
    float var = tot2 * (1.0f / D) - mu * mu;
    float y = (x - mu) * rsqrtf(var + 1e-5f) * ln_g[d] + ln_b[d];
    __nv_bfloat16 yh = __float2bfloat16(y);
    hh[e * D + d] = yh;
    hl[e * D + d] = __float2bfloat16(y - __bfloat162float(yh));
}

// ================= MLP GEMM via HMMA bf16 hi/lo 3-pass (proven) ===============
#define MBM 128
#define MBN 128
#define MBK 64
#define MTILE_B (MBM * MBK * 2)
#define MSTAGE_B (4 * MTILE_B)
#define SMEM_MLP (2 * MSTAGE_B)      // 128 KB

__global__ __launch_bounds__(256, 1)
void k_mlp_mma(const __nv_bfloat16* __restrict__ Ahi, const __nv_bfloat16* __restrict__ Alo,
               const __nv_bfloat16* __restrict__ Bhi, const __nv_bfloat16* __restrict__ Blo,
               const float* __restrict__ bias, int mode,
               __nv_bfloat16* __restrict__ out_hi, __nv_bfloat16* __restrict__ out_lo,
               float* __restrict__ var0, float* __restrict__ var1,
               const int* __restrict__ orders, const int* __restrict__ types, int order) {
    extern __shared__ char smem[];
    const int tid = threadIdx.x;
    const int wid = tid >> 5, lane = tid & 31;
    const int bm = blockIdx.y * MBM;
    const int bn = blockIdx.x * MBN;
    const int wm = (wid & 1) * 64;
    const int wn = (wid >> 1) * 32;
    const uint32_t sbase = smem_u32(smem);

    float acc[4][4][4];
#pragma unroll
    for (int mt = 0; mt < 4; mt++)
#pragma unroll
        for (int nt = 0; nt < 4; nt++)
#pragma unroll
            for (int q = 0; q < 4; q++) acc[mt][nt][q] = 0.0f;

    auto load_stage = [&](int ci, int stg) {
        const int k0 = ci * MBK;
        const uint32_t sst = sbase + (uint32_t)stg * MSTAGE_B;
#pragma unroll
        for (int j = 0; j < 4; j++) {
            int i = tid + j * 256;
            int row = i >> 3, ch = i & 7;
            uint32_t so = swz(row, ch);
            size_t aoff = (size_t)(bm + row) * D + k0 + ch * 8;
            cpa16(sst + 0 * MTILE_B + so, Ahi + aoff, 16);
            cpa16(sst + 1 * MTILE_B + so, Alo + aoff, 16);
            size_t boff = (size_t)(bn + row) * D + k0 + ch * 8;
            cpa16(sst + 2 * MTILE_B + so, Bhi + boff, 16);
            cpa16(sst + 3 * MTILE_B + so, Blo + boff, 16);
        }
        asm volatile("cp.async.commit_group;" ::: "memory");
    };

    load_stage(0, 0);

    const int jj = lane >> 3;
    const int rr = lane & 7;

    const int NCH = D / MBK;   // 4
    for (int ci = 0; ci < NCH; ci++) {
        if (ci + 1 < NCH) {
            load_stage(ci + 1, (ci + 1) & 1);
            asm volatile("cp.async.wait_group 1;" ::: "memory");
        } else {
            asm volatile("cp.async.wait_group 0;" ::: "memory");
        }
        __syncthreads();

        const uint32_t sst = sbase + (uint32_t)(ci & 1) * MSTAGE_B;
#pragma unroll
        for (int kt = 0; kt < 4; kt++) {
            uint32_t a_hi[4][4], a_lo[4][4], b_hi[4][2], b_lo[4][2];
            {
                uint32_t arow = (uint32_t)(wm + (jj & 1) * 8 + rr);
                uint32_t ach = (uint32_t)(kt * 2 + (jj >> 1));
#pragma unroll
                for (int mt = 0; mt < 4; mt++) {
                    uint32_t so = swz(arow + mt * 16, ach);
                    ldsm_x4(a_hi[mt], sst + 0 * MTILE_B + so);
                    ldsm_x4(a_lo[mt], sst + 1 * MTILE_B + so);
                }
            }
            {
                uint32_t bch = (uint32_t)(kt * 2 + ((lane >> 3) & 1));
#pragma unroll
                for (int p = 0; p < 2; p++) {
                    uint32_t brow = (uint32_t)(wn + (2 * p + (lane >> 4)) * 8 + rr);
                    uint32_t so = swz(brow, bch);
                    uint32_t r4[4];
                    ldsm_x4(r4, sst + 2 * MTILE_B + so);
                    b_hi[2 * p][0] = r4[0]; b_hi[2 * p][1] = r4[1];
                    b_hi[2 * p + 1][0] = r4[2]; b_hi[2 * p + 1][1] = r4[3];
                    ldsm_x4(r4, sst + 3 * MTILE_B + so);
                    b_lo[2 * p][0] = r4[0]; b_lo[2 * p][1] = r4[1];
                    b_lo[2 * p + 1][0] = r4[2]; b_lo[2 * p + 1][1] = r4[3];
                }
            }
#pragma unroll
            for (int pass = 0; pass < 3; pass++)
#pragma unroll
                for (int mt = 0; mt < 4; mt++)
#pragma unroll
                    for (int nt = 0; nt < 4; nt++) {
                        const uint32_t* a = (pass == 2) ? a_lo[mt] : a_hi[mt];
                        const uint32_t* b = (pass == 1) ? b_lo[nt] : b_hi[nt];
                        mma16816_bf16(acc[mt][nt], a, b);
                    }
        }
        __syncthreads();
    }

    // ---- epilogue ----
    const int g = lane >> 2;
    const int qc = (lane & 3) * 2;
#pragma unroll
    for (int mt = 0; mt < 4; mt++) {
        int row0 = bm + wm + mt * 16 + g;
#pragma unroll
        for (int nt = 0; nt < 4; nt++) {
            int col = bn + wn + nt * 8 + qc;
            float b0 = bias[col], b1v = bias[col + 1];
            float v00 = acc[mt][nt][0] + b0;
            float v01 = acc[mt][nt][1] + b1v;
            float v10 = acc[mt][nt][2] + b0;
            float v11 = acc[mt][nt][3] + b1v;
            if (mode == 0) {
                v00 = fmaxf(v00, 0.0f); v01 = fmaxf(v01, 0.0f);
                v10 = fmaxf(v10, 0.0f); v11 = fmaxf(v11, 0.0f);
#pragma unroll
                for (int hrow = 0; hrow < 2; hrow++) {
                    int r = row0 + hrow * 8;
                    float a = hrow ? v10 : v00;
                    float b = hrow ? v11 : v01;
                    __nv_bfloat16 ah = __float2bfloat16(a);
                    __nv_bfloat16 bh = __float2bfloat16(b);
                    out_hi[(size_t)r * D + col] = ah;
                    out_hi[(size_t)r * D + col + 1] = bh;
                    out_lo[(size_t)r * D + col] = __float2bfloat16(a - __bfloat162float(ah));
                    out_lo[(size_t)r * D + col + 1] = __float2bfloat16(b - __bfloat162float(bh));
                }
            } else {
                v00 = 1.0f / (1.0f + __expf(-v00));
                v01 = 1.0f / (1.0f + __expf(-v01));
                v10 = 1.0f / (1.0f + __expf(-v10));
                v11 = 1.0f / (1.0f + __expf(-v11));
#pragma unroll
                for (int hrow = 0; hrow < 2; hrow++) {
                    int e = row0 + hrow * 8;
                    if (orders[e] == order) {
                        float a = hrow ? v10 : v00;
                        float b = hrow ? v11 : v01;
                        var0[(size_t)e * D + col] = a;
                        var0[(size_t)e * D + col + 1] = b;
                        bool neg = (types[e] == 1);
                        var1[(size_t)e * D + col] = neg ? (1.0f - a) : a;
                        var1[(size_t)e * D + col + 1] = neg ? (1.0f - b) : b;
                    }
                }
            }
        }
    }
}

// ---------------- conjunction ----------------
__global__ void k_conj(const float* __restrict__ var0, const float* __restrict__ var1,
                       const int* __restrict__ orders, const int* __restrict__ types,
                       const int* __restrict__ lin, const int* __restrict__ lib,
                       int order, float* __restrict__ tmpC) {
    int e = blockIdx.x;
    if (orders[e] != order || types[e] != 2) return;
    int d = threadIdx.x;
    float p = var0[e * D + d];
#pragma unroll
    for (int a = 1; a < 4; a++) {
        if (lin[a * E_EDGES + e] >= 0) {
            int j = lib[a * E_EDGES + e];
            j = max(0, min(E_EDGES - 1, j));
            p *= var1[j * D + d];
        }
    }
    tmpC[e * D + d] = p;
}

// ---------------- disjunction (sees post-conj var1 via tmpC redirect) ----------------
__global__ void k_disj(const float* __restrict__ var0, const float* __restrict__ var1,
                       const int* __restrict__ orders, const int* __restrict__ types,
                       const int* __restrict__ lin, const int* __restrict__ lib,
                       int order, const float* __restrict__ tmpC, float* __restrict__ tmpD) {
    int e = blockIdx.x;
    if (orders[e] != order || types[e] != 3) return;
    int d = threadIdx.x;
    float q = 1.0f - var0[e * D + d];
#pragma unroll
    for (int a = 1; a < 4; a++) {
        if (lin[a * E_EDGES + e] >= 0) {
            int j = lib[a * E_EDGES + e];
            j = max(0, min(E_EDGES - 1, j));
            float v = (orders[j] == order && types[j] == 2) ? tmpC[j * D + d]
                                                           : var1[j * D + d];
            q *= (1.0f - v);
        }
    }
    tmpD[e * D + d] = 1.0f - q;
}

// ---------------- apply conj/disj ----------------
__global__ void k_apply(const int* __restrict__ orders, const int* __restrict__ types,
                        int order, const float* __restrict__ tmpC,
                        const float* __restrict__ tmpD, float* __restrict__ var1) {
    int e = blockIdx.x;
    if (orders[e] != order) return;
    int ty = types[e];
    int d = threadIdx.x;
    if (ty == 2) var1[e * D + d] = tmpC[e * D + d];
    else if (ty == 3) var1[e * D + d] = tmpD[e * D + d];
}

// ================= vocab GEMM: fp16 2-pass (A hi/lo, B single) ================
#define BMT 128
#define BNT 128
#define BKT 64
#define TILE_B (BMT * BKT * 2)
#define STAGE_B (3 * TILE_B)         // Ah, Al, B = 48 KB
#define SMEM_GEMM (2 * STAGE_B)      // 96 KB double-buffered

__global__ __launch_bounds__(256, 1)
void k_gemm_mma(const __half* __restrict__ Ah, const __half* __restrict__ Al,
                const __half* __restrict__ Bh, float* __restrict__ C) {
    extern __shared__ char smem[];
    const int tid = threadIdx.x;
    const int wid = tid >> 5, lane = tid & 31;
    const int bm = blockIdx.y * BMT;
    const int bn = blockIdx.x * BNT;
    const int wm = (wid & 1) * 64;
    const int wn = (wid >> 1) * 32;
    const uint32_t sbase = smem_u32(smem);

    float acc[4][4][4];
#pragma unroll
    for (int mt = 0; mt < 4; mt++)
#pragma unroll
        for (int nt = 0; nt < 4; nt++)
#pragma unroll
            for (int q = 0; q < 4; q++) acc[mt][nt][q] = 0.0f;

    auto load_stage = [&](int ci, int stg) {
        const int k0 = ci * BKT;
        const uint32_t sst = sbase + (uint32_t)stg * STAGE_B;
#pragma unroll
        for (int j = 0; j < 4; j++) {
            int i = tid + j * 256;
            int row = i >> 3, ch = i & 7;
            uint32_t so = swz(row, ch);
            size_t aoff = (size_t)(bm + row) * D + k0 + ch * 8;
            cpa16(sst + 0 * TILE_B + so, Ah + aoff, 16);
            cpa16(sst + 1 * TILE_B + so, Al + aoff, 16);
            int brow = bn + row;
            uint32_t bs = (brow < VOCAB) ? 16u : 0u;
            size_t boff = (size_t)min(brow, VOCAB - 1) * D + k0 + ch * 8;
            cpa16(sst + 2 * TILE_B + so, Bh + boff, bs);
        }
        asm volatile("cp.async.commit_group;" ::: "memory");
    };

    load_stage(0, 0);

    const int jj = lane >> 3;
    const int rr = lane & 7;

    const int NCH = D / BKT;
    for (int ci = 0; ci < NCH; ci++) {
        if (ci + 1 < NCH) {
            load_stage(ci + 1, (ci + 1) & 1);
            asm volatile("cp.async.wait_group 1;" ::: "memory");
        } else {
            asm volatile("cp.async.wait_group 0;" ::: "memory");
        }
        __syncthreads();

        const uint32_t sst = sbase + (uint32_t)(ci & 1) * STAGE_B;
#pragma unroll
        for (int kt = 0; kt < 4; kt++) {
            uint32_t a_hi[4][4], a_lo[4][4], b[4][2];
            {
                uint32_t arow = (uint32_t)(wm + (jj & 1) * 8 + rr);
                uint32_t ach = (uint32_t)(kt * 2 + (jj >> 1));
#pragma unroll
                for (int mt = 0; mt < 4; mt++) {
                    uint32_t so = swz(arow + mt * 16, ach);
                    ldsm_x4(a_hi[mt], sst + 0 * TILE_B + so);
                    ldsm_x4(a_lo[mt], sst + 1 * TILE_B + so);
                }
            }
            {
                uint32_t bch = (uint32_t)(kt * 2 + ((lane >> 3) & 1));
#pragma unroll
                for (int p = 0; p < 2; p++) {
                    uint32_t brow = (uint32_t)(wn + (2 * p + (lane >> 4)) * 8 + rr);
                    uint32_t so = swz(brow, bch);
                    uint32_t r4[4];
                    ldsm_x4(r4, sst + 2 * TILE_B + so);
                    b[2 * p][0] = r4[0]; b[2 * p][1] = r4[1];
                    b[2 * p + 1][0] = r4[2]; b[2 * p + 1][1] = r4[3];
                }
            }
            // 2 passes: Ah*B, Al*B — pass-outer keeps accumulator reuse distance 16
#pragma unroll
            for (int pass = 0; pass < 2; pass++)
#pragma unroll
                for (int mt = 0; mt < 4; mt++)
#pragma unroll
                    for (int nt = 0; nt < 4; nt++) {
                        const uint32_t* a = pass ? a_lo[mt] : a_hi[mt];
                        mma16816_f16(acc[mt][nt], a, b[nt]);
                    }
        }
        __syncthreads();
    }

    // ---- epilogue: SCALAR stores (C base is 4B-aligned only: out+1) ----
    const int g = lane >> 2;
    const int qc = (lane & 3) * 2;
#pragma unroll
    for (int mt = 0; mt < 4; mt++) {
        int row0 = bm + wm + mt * 16 + g;
#pragma unroll
        for (int nt = 0; nt < 4; nt++) {
            int col = bn + wn + nt * 8 + qc;
            if (col < VOCAB) {
                float* p0 = &C[(size_t)row0 * VOCAB + col];
                float* p1 = &C[(size_t)(row0 + 8) * VOCAB + col];
                p0[0] = acc[mt][nt][0];
                p0[1] = acc[mt][nt][1];
                p1[0] = acc[mt][nt][2];
                p1[1] = acc[mt][nt][3];
            }
        }
    }
}

// ---------------- per-row soft-label CE via online logsumexp ----------------
__global__ void k_rowloss(const float* __restrict__ logits,
                          const int* __restrict__ answers,
                          const int* __restrict__ mask_type,
                          float* __restrict__ rowloss) {
    int e = blockIdx.x;
    const float* row = logits + (size_t)e * VOCAB;
    int t = threadIdx.x;
    float m = -1e30f, s = 0.0f, sx = 0.0f;
    for (int v = t; v < VOCAB; v += 256) {
        float x = row[v];
        sx += x;
        float mn = fmaxf(m, x);
        s = s * __expf(m - mn) + __expf(x - mn);
        m = mn;
    }
    __shared__ float shm[256], shs[256], shx[256];
    shm[t] = m; shs[t] = s; shx[t] = sx;
    __syncthreads();
    for (int off = 128; off > 0; off >>= 1) {
        if (t < off) {
            float m2 = shm[t + off], s2 = shs[t + off];
            float mn = fmaxf(shm[t], m2);
            shs[t] = shs[t] * __expf(shm[t] - mn) + s2 * __expf(m2 - mn);
            shm[t] = mn;
            shx[t] += shx[t + off];
        }
        __syncthreads();
    }
    if (t == 0) {
        float lse = shm[0] + logf(shs[0]);
        float sumx = shx[0];
        float la = row[answers[e]] - lse;
        float soft = (mask_type[e] > 0) ? 0.9f : 1.0f;
        float loss = -(soft * la +
                       (1.0f - soft) * (1.0f / (float)(VOCAB - 1)) *
                           ((sumx - (float)VOCAB * lse) - la));
        rowloss[e] = loss;
    }
}

__global__ void k_finalloss(const float* __restrict__ rowloss, float* __restrict__ out) {
    __shared__ float sh[256];
    float a = 0.0f;
    for (int i = threadIdx.x; i < E_EDGES; i += 256) a += rowloss[i];
    sh[threadIdx.x] = a;
    __syncthreads();
    for (int off = 128; off > 0; off >>= 1) {
        if (threadIdx.x < off) sh[threadIdx.x] += sh[threadIdx.x + off];
        __syncthreads();
    }
    if (threadIdx.x == 0) out[0] = sh[0] * (1.0f / (float)E_EDGES);
}

// ---------------- launch ----------------
extern "C" void kernel_launch(void* const* d_in, const int* in_sizes, int n_in,
                              void* d_out, int out_size) {
    const float* node_emb   = (const float*)d_in[0];
    const int*   input_ids  = (const int*)d_in[1];
    const float* input_mask = (const float*)d_in[2];
    const int*   edge_ord   = (const int*)d_in[3];
    const int*   vim        = (const int*)d_in[4];
    const int*   vibm       = (const int*)d_in[5];
    const int*   out_pos    = (const int*)d_in[6];
    const int*   lin        = (const int*)d_in[7];
    const int*   lib        = (const int*)d_in[8];
    const int*   ltypes     = (const int*)d_in[9];
    const int*   answers    = (const int*)d_in[10];
    const int*   mask_type  = (const int*)d_in[11];
    const float* W1         = (const float*)d_in[12];
    const float* b1         = (const float*)d_in[13];
    const float* W2         = (const float*)d_in[14];
    const float* b2         = (const float*)d_in[15];
    const float* ln_g       = (const float*)d_in[16];
    const float* ln_b       = (const float*)d_in[17];

    float* out = (float*)d_out;
    long long loff = (long long)out_size - (long long)E_EDGES * VOCAB;
    if (loff < 0) loff = 0;
    float* logits = out + loff;

    float *var0, *var1, *tmpC, *tmpD, *rowloss;
    __half *Ah, *Al, *Bh;
    __nv_bfloat16 *hh, *hl, *hidh, *hidl, *W1th, *W1tl, *W2th, *W2tl;
    cudaGetSymbolAddress((void**)&var0, g_var0);
    cudaGetSymbolAddress((void**)&var1, g_var1);
    cudaGetSymbolAddress((void**)&tmpC, g_tmpC);
    cudaGetSymbolAddress((void**)&tmpD, g_tmpD);
    cudaGetSymbolAddress((void**)&rowloss, g_rowloss);
    cudaGetSymbolAddress((void**)&Ah, g_Ah);
    cudaGetSymbolAddress((void**)&Al, g_Al);
    cudaGetSymbolAddress((void**)&Bh, g_Bh);
    cudaGetSymbolAddress((void**)&hh, g_hh);
    cudaGetSymbolAddress((void**)&hl, g_hl);
    cudaGetSymbolAddress((void**)&hidh, g_hidh);
    cudaGetSymbolAddress((void**)&hidl, g_hidl);
    cudaGetSymbolAddress((void**)&W1th, g_W1th);
    cudaGetSymbolAddress((void**)&W1tl, g_W1tl);
    cudaGetSymbolAddress((void**)&W2th, g_W2th);
    cudaGetSymbolAddress((void**)&W2tl, g_W2tl);

    cudaFuncSetAttribute(k_gemm_mma, cudaFuncAttributeMaxDynamicSharedMemorySize,
                         SMEM_GEMM);
    cudaFuncSetAttribute(k_mlp_mma, cudaFuncAttributeMaxDynamicSharedMemorySize,
                         SMEM_MLP);

    k_init<<<(E_EDGES * D) / 256, 256>>>(var0, var1);
    k_splitB_h<<<(VOCAB * D + 255) / 256, 256>>>(node_emb, Bh, VOCAB * D);
    k_splitT2<<<512, 256>>>(W1, W2, W1th, W1tl, W2th, W2tl);

    dim3 mgrid(2, E_EDGES / MBM);
    for (int order = 0; order < NUM_ORDERS; ++order) {
        k_encoder<<<E_EDGES, 256>>>(node_emb, input_ids, input_mask, vim, vibm,
                                    out_pos, ln_g, ln_b, var1, hh, hl);
        k_mlp_mma<<<mgrid, 256, SMEM_MLP>>>(hh, hl, W1th, W1tl, b1, 0,
                                            hidh, hidl, nullptr, nullptr,
                                            nullptr, nullptr, 0);
        k_mlp_mma<<<mgrid, 256, SMEM_MLP>>>(hidh, hidl, W2th, W2tl, b2, 1,
                                            nullptr, nullptr, var0, var1,
                                            edge_ord, ltypes, order);
        k_conj<<<E_EDGES, 256>>>(var0, var1, edge_ord, ltypes, lin, lib, order, tmpC);
        k_disj<<<E_EDGES, 256>>>(var0, var1, edge_ord, ltypes, lin, lib, order, tmpC, tmpD);
        k_apply<<<E_EDGES, 256>>>(edge_ord, ltypes, order, tmpC, tmpD, var1);
    }

    k_splitA_h<<<(E_EDGES * D + 255) / 256, 256>>>(var1, Ah, Al, E_EDGES * D);

    dim3 grid((VOCAB + BNT - 1) / BNT, E_EDGES / BMT);
    k_gemm_mma<<<grid, 256, SMEM_GEMM>>>(Ah, Al, Bh, logits);

    if (loff >= 1) {
        k_rowloss<<<E_EDGES, 256>>>(logits, answers, mask_type, rowloss);
        k_finalloss<<<1, 256>>>(rowloss, out);
    }
}